// round 15
// baseline (speedup 1.0000x reference)
#include <cuda_runtime.h>
#include <cstdint>

// ---------------------------------------------------------------------------
// TDGSPooling2d: hard Gumbel-softmax 2x2 pooling (K=2, stride 2).
// out = x[argmax over patch of (x/temp_relu_eps + gumbel)]
// gumbel bits: JAX threefry2x32, key=(0,42), partitionable (bits = o0^o1 of
// threefry(hi=0, lo=flat_index)).
// Pipe balancing (empirical optimum R4-R13): threefry adds forced to IMAD
// (fma pipe) via opaque 'one'; round 1 elided; exactly 3 rotates in mul-form
// (IMAD.LO+IMAD.HI + fused LOP3), rest SHF. Uniform via I2F + FFMA.
// Scoring in the t-multiplied lg2 domain (no div/rcp on the fast path).
// Guard via FMNMX second-max tree; certified error bound (single rcp of
// zmin); precise (IEEE div + libdevice logf) fallback -- bit-exact vs XLA.
// 8 outputs/thread: (wo, wo+1) x 4 batches -- temperature, index decode and
// all per-thread setup amortized over 8 outputs (temp is b-independent).
// Batch loop is #pragma unroll 1 to keep regs <= 40 (8 blocks/SM).
// 3D grid (7, C, B/4) x (28, 8): zero integer divisions.
// ---------------------------------------------------------------------------

constexpr int B  = 32;
constexpr int C  = 128;
constexpr int H  = 112;
constexpr int W  = 112;
constexpr int Ho = 56;
constexpr int Wo = 56;
constexpr int P   = C * Ho * Wo;   // 401408
constexpr int XPB = C * H * W;     // 1605632

__device__ __forceinline__ unsigned rotl32(unsigned x, int r) {
    return __funnelshift_l(x, x, r);          // SHF (alu)
}

// d = a*one + c  -> IMAD on the fma pipe ('one' is an opaque runtime 1)
__device__ __forceinline__ unsigned mad1(unsigned a, unsigned one, unsigned c) {
    unsigned d;
    asm("mad.lo.u32 %0, %1, %2, %3;" : "=r"(d) : "r"(a), "r"(one), "r"(c));
    return d;
}
// d = one*imm + c  -> IMAD (imm multiplier) on the fma pipe
#define MAD1I(one, imm, c) ({                                   \
    unsigned d_;                                                \
    asm("mad.lo.u32 %0, %1, %2, %3;"                            \
        : "=r"(d_) : "r"(one), "n"(imm), "r"(c));               \
    d_; })

// (lo | hi) ^ c in one LOP3 (LUT: (0xF0|0xCC)^0xAA = 0x56)
__device__ __forceinline__ unsigned or_xor(unsigned lo, unsigned hi, unsigned c) {
    unsigned d;
    asm("lop3.b32 %0, %1, %2, %3, 0x56;" : "=r"(d) : "r"(lo), "r"(hi), "r"(c));
    return d;
}
// lo = a*m (register multiplier -> IMAD, cannot be strength-reduced)
__device__ __forceinline__ unsigned mul_lo(unsigned a, unsigned m) {
    unsigned d;
    asm("mad.lo.u32 %0, %1, %2, %3;" : "=r"(d) : "r"(a), "r"(m), "n"(0));
    return d;
}

struct Po2 { unsigned p29, p16a, p16b; };   // opaque 2^r values

// Threefry-2x32, 20 rounds, key=(0,42), constants folded, fold o0^o1.
// Entry e must equal counter + 42 (first key injection pre-applied).
// Round 1 elided (x0 starts at 0). Three rotates in mul-form (fma pipe).
__device__ __forceinline__ unsigned tf_fold_entry(unsigned e, unsigned one,
                                                  const Po2& p) {
    const unsigned ks1 = 42u;
    const unsigned ks2 = 0x1BD11BDAu ^ 42u;
    unsigned x0 = e;
    unsigned x1 = rotl32(e, 13) ^ e;
#define TF_R(r) { x0 = mad1(x1, one, x0); x1 = rotl32(x1, (r)); x1 ^= x0; }
#define TF_RM(pw) { x0 = mad1(x1, one, x0);                      \
    unsigned lo_ = mul_lo(x1, pw);                               \
    unsigned hi_ = __umulhi(x1, pw);                             \
    x1 = or_xor(lo_, hi_, x0); }
    TF_R(15) TF_R(26) TF_R(6)
    x0 = MAD1I(one, ks1, x0);        x1 = MAD1I(one, (ks2 + 1u), x1);
    TF_R(17) TF_RM(p.p29) TF_RM(p.p16a) TF_R(24)
    x0 = MAD1I(one, ks2, x0);        x1 = MAD1I(one, 2u, x1);
    TF_R(13) TF_R(15) TF_R(26) TF_R(6)
    /* x0 += 0 */                    x1 = MAD1I(one, (ks1 + 3u), x1);
    TF_R(17) TF_R(29) TF_RM(p.p16b) TF_R(24)
    x0 = MAD1I(one, ks1, x0);        x1 = MAD1I(one, (ks2 + 4u), x1);
    TF_R(13) TF_R(15) TF_R(26) TF_R(6)
    x0 = MAD1I(one, ks2, x0);        x1 = MAD1I(one, 5u, x1);
#undef TF_R
#undef TF_RM
    return x0 ^ x1;
}

__device__ __forceinline__ float rcp_approx(float a) {
    float r;
    asm("rcp.approx.f32 %0, %1;" : "=f"(r) : "f"(a));
    return r;
}

// One output: 4 hashes + argmax over 4 of (x/t + gumbel).
// Fast path scores s_k = x_k + na*lg2|lg2(u_k)| (na = -t*ln2): same argmax
// as x/t + g up to shared scale/shift. Second-max FMNMX guard with certified
// bound; precise fallback bit-identical to XLA.
__device__ __forceinline__ float pool_one(float xv0, float xv1, float xv2,
                                          float xv3, float t, float na,
                                          unsigned ebase, unsigned one,
                                          const Po2& p) {
    const float xv[4] = {xv0, xv1, xv2, xv3};

    float uu[4], ss[4], za[4];
#pragma unroll
    for (int k = 0; k < 4; k++) {
        unsigned bits = tf_fold_entry(
            k == 0 ? ebase : mad1((unsigned)k, one, ebase), one, p);
        // uniform == XLA exactly: h = bits>>9 (umulhi, exact);
        // XLA's (bitcast((bits>>9)|0x3F800000) - 1) is exactly h*2^-23
        // (Sterbenz), so u = rn(h*2^-23 + 1e-20) -- one I2F + one FFMA.
        unsigned h = __umulhi(bits, 1u << 23);          // IMAD.HI
        float f = __uint2float_rn(h);                   // I2F, exact (h<2^23)
        float u = fmaf(f, 0x1p-23f, 1e-20f);            // == XLA uniform
        uu[k] = u;
        // z = |lg2(u)| (free modifier). MUFU corner cases near u~1 give tiny
        // z -> rcp(zmin) huge -> emax huge/NaN -> guard fails -> fallback.
        float z = fabsf(__log2f(u));
        za[k] = z;
        float w = __log2f(z);
        ss[k] = fmaf(w, na, xv[k]);
    }

    // max + second-max via FMNMX tree
    float a  = fmaxf(ss[0], ss[1]), bb = fminf(ss[0], ss[1]);
    float cc = fmaxf(ss[2], ss[3]), dd = fminf(ss[2], ss[3]);
    float mx = fmaxf(a, cc);
    float m2 = fmaxf(fminf(a, cc), fmaxf(bb, dd));

    // certified |ss_k - (t*l_XLA_k + C)| bound, monotone in 1/z -> one rcp
    // of zmin covers all draws; folds MUFU rel terms, XLA-side div/logf
    // rounding (x t), and the fl(t*ln2) skew, >=2x slack.
    float zmin = fminf(fminf(za[0], za[1]), fminf(za[2], za[3]));
    float emax = fmaf(5e-6f, rcp_approx(zmin), 1e-4f);
    float thr = fmaf(-2.0f, emax, mx);

    float bx;
    if (m2 < thr) {
        // unique, well-separated max: select by equality against mx
        bx = xv[3];
        if (ss[2] == mx) bx = xv[2];
        if (ss[1] == mx) bx = xv[1];
        if (ss[0] == mx) bx = xv[0];
    } else {
        // precise path: IEEE div + libdevice logf -- bit-identical to XLA
        float l0 = xv[0] / t + (-logf(-logf(uu[0])));
        float l1 = xv[1] / t + (-logf(-logf(uu[1])));
        float l2 = xv[2] / t + (-logf(-logf(uu[2])));
        float l3 = xv[3] / t + (-logf(-logf(uu[3])));
        float bv = l0; bx = xv[0];
        if (l1 > bv) { bv = l1; bx = xv[1]; }
        if (l2 > bv) { bv = l2; bx = xv[2]; }
        if (l3 > bv) { bv = l3; bx = xv[3]; }
    }
    return bx;
}

// Two outputs (wo, wo+1) for one batch image: float4 patch rows.
__device__ __forceinline__ float2 pool_pair(const float* __restrict__ xp,
                                            float t0, float na0,
                                            float t1, float na1,
                                            unsigned e0, unsigned one,
                                            const Po2& p) {
    float4 row0 = *reinterpret_cast<const float4*>(xp);      // row 2ho
    float4 row1 = *reinterpret_cast<const float4*>(xp + W);  // row 2ho+1
    float o0 = pool_one(row0.x, row0.y, row1.x, row1.y, t0, na0, e0, one, p);
    float o1 = pool_one(row0.z, row0.w, row1.z, row1.w, t1, na1,
                        MAD1I(one, 4u, e0), one, p);
    return make_float2(o0, o1);
}

// grid (7, C, B/4), block (28, 8): ho = 8*bx + ty, wo pair = 2*tx,
// batches (4*bz .. 4*bz+3). No integer divisions.
__global__ __launch_bounds__(224, 8) void tdgs_pool_kernel(
        const float* __restrict__ x,
        const float* __restrict__ temperature,
        float* __restrict__ out,
        unsigned one) {                 // opaque 1 (defeats const-prop)
    int c  = blockIdx.y;
    int b0 = blockIdx.z * 4;
    int ho = blockIdx.x * 8 + threadIdx.y;
    int tx = threadIdx.x;               // 0..27, output pair (2tx, 2tx+1)

    Po2 p;                              // opaque 2^r rotate multipliers
    p.p29  = one << 29;
    p.p16a = one << 16;
    p.p16b = p.p16a;

    int r0 = (c * Ho + ho) * Wo + 2 * tx;          // temp / out row index

    float2 t2 = *reinterpret_cast<const float2*>(temperature + r0);
    float t0 = fmaxf(t2.x, 0.0f) + 0.1f;
    float t1 = fmaxf(t2.y, 0.0f) + 0.1f;
    float na0 = t0 * -0.69314718056f;   // -t*ln2 (shared scale, fast path)
    float na1 = t1 * -0.69314718056f;

    const float* xp = x + (size_t)b0 * XPB + (c * H + 2 * ho) * W + 4 * tx;
    float* op = out + (size_t)b0 * P + r0;

    unsigned e = MAD1I(one, 42u,
                       4u * ((unsigned)b0 * (unsigned)P + (unsigned)r0));

#pragma unroll 1
    for (int bi = 0; bi < 4; bi++) {
        float2 res = pool_pair(xp, t0, na0, t1, na1, e, one, p);
        *reinterpret_cast<float2*>(op) = res;
        xp += XPB;                       // next batch image
        op += P;
        e = MAD1I(one, 4u * (unsigned)P, e);   // counters shift by 4*P
    }
}

extern "C" void kernel_launch(void* const* d_in, const int* in_sizes, int n_in,
                              void* d_out, int out_size) {
    const float* x    = (const float*)d_in[0];   // (32,128,112,112) f32
    const float* temp = (const float*)d_in[1];   // (128,56,56) f32
    float* out        = (float*)d_out;           // (32,128,56,56) f32
    (void)in_sizes; (void)n_in; (void)out_size;

    tdgs_pool_kernel<<<dim3(7, C, B / 4), dim3(28, 8)>>>(x, temp, out, 1u);
}